// round 14
// baseline (speedup 1.0000x reference)
#include <cuda_runtime.h>
#include <math.h>

#define B_    8
#define NIN   32
#define H_    14
#define CIN   8
#define C_    32
#define COUT  16
#define W_    12
#define R_    288
#define SB    8          // sites per CTA
#define RS    290        // padded r-stride for P in smem
#define NT    512

// smem: P [SB][COUT][RS] floats, then win [SB][R_][CIN] floats.
// After P-compute, the win region is reused for a[SB][R_], v[SB][COUT], red[SB][2][17].
#define SM_FLOATS (SB*COUT*RS + SB*R_*CIN)

__global__ __launch_bounds__(NT, 1)
void caps_kernel(const float* __restrict__ x,
                 const float* __restrict__ rw,
                 float* __restrict__ out)
{
    extern __shared__ float sm[];
    float* Ps  = sm;                        // [SB][COUT][RS]
    float* win = sm + SB*COUT*RS;           // [SB][R_][CIN]
    float* a_s = win;                       // alias (win dead after P-compute)
    float* v_s = win + SB*R_;               // [SB][COUT]
    float* red = v_s + SB*COUT;             // [SB][2][17]

    const int tid = threadIdx.x;
    const int sb  = blockIdx.x;             // site block 0..143
    const int c   = blockIdx.y;             // capsule class 0..31

    // ---------------- load x windows into smem (float4 granules) -------------
    for (int f = tid; f < SB*R_*2; f += NT) {
        int s    = f / (R_*2);
        int rr2  = f - s*(R_*2);
        int r    = rr2 >> 1;
        int half = rr2 & 1;
        int site = sb*SB + s;
        int b    = site / (W_*W_);
        int rem  = site - b*(W_*W_);
        int p    = rem / W_;
        int q    = rem - p*W_;
        int nin  = r / 9;
        int k9   = r - nin*9;
        int kr   = k9 / 3;
        int kc   = k9 - kr*3;
        const float4 t = *reinterpret_cast<const float4*>(
            x + ((((size_t)(b*NIN + nin)*H_ + (p+kr))*H_ + (q+kc))*CIN + half*4));
        *reinterpret_cast<float4*>(win + ((s*R_ + r)*CIN + half*4)) = t;
    }
    __syncthreads();

    // ---------------- P[s][o][r] = sum_i win[s][r][i] * rw[c][r][i][o] -------
    const float* rwc = rw + (size_t)c * R_ * CIN * COUT;
    for (int item = tid; item < R_*8; item += NT) {
        int r  = item >> 3;
        int s4 = (item >> 2) & 1;            // site half (sites 0-3 / 4-7)
        int o4 = item & 3;                   // output quad
        float Wv[CIN][4];
        const float* wp = rwc + (size_t)r*CIN*COUT + o4*4;
        #pragma unroll
        for (int i = 0; i < CIN; i++) {
            float4 t = *reinterpret_cast<const float4*>(wp + i*COUT);
            Wv[i][0]=t.x; Wv[i][1]=t.y; Wv[i][2]=t.z; Wv[i][3]=t.w;
        }
        #pragma unroll
        for (int ss = 0; ss < 4; ss++) {
            int s = s4*4 + ss;
            const float* wrow = win + (s*R_ + r)*CIN;
            float4 wa = *reinterpret_cast<const float4*>(wrow);
            float4 wb = *reinterpret_cast<const float4*>(wrow + 4);
            #pragma unroll
            for (int j = 0; j < 4; j++) {
                float acc =      wa.x * Wv[0][j];
                acc = fmaf(wa.y, Wv[1][j], acc);
                acc = fmaf(wa.z, Wv[2][j], acc);
                acc = fmaf(wa.w, Wv[3][j], acc);
                acc = fmaf(wb.x, Wv[4][j], acc);
                acc = fmaf(wb.y, Wv[5][j], acc);
                acc = fmaf(wb.z, Wv[6][j], acc);
                acc = fmaf(wb.w, Wv[7][j], acc);
                Ps[(s*COUT + o4*4 + j)*RS + r] = acc;
            }
        }
    }
    __syncthreads();   // win region now dead -> reused as a_s/v_s/red

    // ---------------- dynamic routing: 3 fused passes over P -----------------
    // pass 0: s = mean_r P            -> v0
    // pass 1: a1 = P·v0 (store), s = softmax(a1)-weighted sum -> v1
    // pass 2: a2 = a1 + P·v1,        s = softmax(a2)-weighted sum -> v2 = out
    const int sloc = tid >> 6;          // site 0..7 (2 warps per site)
    const int lane = tid & 63;          // r = lane + 64j
    const int wh   = (tid >> 5) & 1;    // which warp within the site group

    float v_reg[COUT];
    #pragma unroll
    for (int o = 0; o < COUT; o++) v_reg[o] = 0.f;

    for (int pass = 0; pass < 3; pass++) {
        if (pass > 0) {
            #pragma unroll
            for (int o = 0; o < COUT; o++) v_reg[o] = v_s[sloc*COUT + o];
        }
        float zloc = 0.f;
        float sv[COUT];
        #pragma unroll
        for (int o = 0; o < COUT; o++) sv[o] = 0.f;

        for (int r = lane; r < R_; r += 64) {
            float pv[COUT];
            #pragma unroll
            for (int o = 0; o < COUT; o++) pv[o] = Ps[(sloc*COUT + o)*RS + r];
            if (pass == 0) {
                #pragma unroll
                for (int o = 0; o < COUT; o++) sv[o] += pv[o];
            } else {
                float dot = 0.f;
                #pragma unroll
                for (int o = 0; o < COUT; o++) dot = fmaf(pv[o], v_reg[o], dot);
                float an = dot;
                if (pass == 2) an += a_s[sloc*R_ + r];
                else           a_s[sloc*R_ + r] = an;
                float e = __expf(an - 10.0f);   // fixed shift; cancels in ratio
                zloc += e;
                #pragma unroll
                for (int o = 0; o < COUT; o++) sv[o] = fmaf(e, pv[o], sv[o]);
            }
        }

        // reduce (z, sv[16]) across each warp
        #pragma unroll
        for (int off = 16; off > 0; off >>= 1) {
            zloc += __shfl_xor_sync(0xffffffffu, zloc, off);
            #pragma unroll
            for (int o = 0; o < COUT; o++)
                sv[o] += __shfl_xor_sync(0xffffffffu, sv[o], off);
        }
        if ((tid & 31) == 0) {
            float* rp = red + (sloc*2 + wh)*17;
            rp[0] = zloc;
            #pragma unroll
            for (int o = 0; o < COUT; o++) rp[1+o] = sv[o];
        }
        __syncthreads();

        // finalize: 128 threads, one per (site, o); squash via 16-lane shuffles
        if (tid < SB*COUT) {
            int s = tid >> 4;
            int o = tid & 15;
            float Z  = red[(s*2)*17]         + red[(s*2+1)*17];
            float so = red[(s*2)*17 + 1 + o] + red[(s*2+1)*17 + 1 + o];
            so *= (pass == 0) ? (1.0f/(float)R_) : (1.0f/Z);
            float sn = so*so;
            #pragma unroll
            for (int off = 8; off > 0; off >>= 1)
                sn += __shfl_xor_sync(0xffffffffu, sn, off);
            float vv = so * (sqrtf(sn) / (1.0f + sn));
            if (pass < 2) {
                v_s[s*COUT + o] = vv;
            } else {
                int site = sb*SB + s;
                int b    = site / (W_*W_);
                int rem  = site - b*(W_*W_);
                int p    = rem / W_;
                int q    = rem - p*W_;
                // out layout: (B, C, w, w, Cout)
                out[((((size_t)b*C_ + c)*W_ + p)*W_ + q)*COUT + o] = vv;
            }
        }
        __syncthreads();
    }
}

extern "C" void kernel_launch(void* const* d_in, const int* in_sizes, int n_in,
                              void* d_out, int out_size)
{
    const float* x  = (const float*)d_in[0];
    const float* rw = (const float*)d_in[1];
    // defensive: identify by element count (x=401408, rw=1179648)
    if (n_in >= 2 && in_sizes[0] == C_*R_*CIN*COUT) {
        const float* t = x; x = rw; rw = t;
    }
    float* out = (float*)d_out;

    const size_t smem = (size_t)SM_FLOATS * sizeof(float);   // 222,208 B
    cudaFuncSetAttribute(caps_kernel,
                         cudaFuncAttributeMaxDynamicSharedMemorySize, (int)smem);

    dim3 grid(B_*W_*W_/SB, C_);   // (144, 32) = 4608 CTAs
    caps_kernel<<<grid, NT, smem>>>(x, rw, out);
}

// round 15
// speedup vs baseline: 1.0004x; 1.0004x over previous
#include <cuda_runtime.h>
#include <math.h>

#define B_    8
#define NIN   32
#define H_    14
#define CIN   8
#define C_    32
#define COUT  16
#define W_    12
#define R_    288
#define SB    8          // sites per CTA
#define RS    290        // padded r-stride for P in smem
#define NT    512

// smem: P [SB][COUT][RS] floats, then win [SB][R_][CIN] floats.
// After P-compute, the win region is reused for a[SB][R_], v[SB][COUT], red[SB][2][17].
#define SM_FLOATS (SB*COUT*RS + SB*R_*CIN)

__global__ __launch_bounds__(NT, 1)
void caps_kernel(const float* __restrict__ x,
                 const float* __restrict__ rw,
                 float* __restrict__ out)
{
    extern __shared__ float sm[];
    float* Ps  = sm;                        // [SB][COUT][RS]
    float* win = sm + SB*COUT*RS;           // [SB][R_][CIN]
    float* a_s = win;                       // alias (win dead after P-compute)
    float* v_s = win + SB*R_;               // [SB][COUT]
    float* red = v_s + SB*COUT;             // [SB][2][17]

    const int tid = threadIdx.x;
    const int sb  = blockIdx.x;             // site block 0..143
    const int c   = blockIdx.y;             // capsule class 0..31

    // ---------------- load x windows into smem (float4 granules) -------------
    for (int f = tid; f < SB*R_*2; f += NT) {
        int s    = f / (R_*2);
        int rr2  = f - s*(R_*2);
        int r    = rr2 >> 1;
        int half = rr2 & 1;
        int site = sb*SB + s;
        int b    = site / (W_*W_);
        int rem  = site - b*(W_*W_);
        int p    = rem / W_;
        int q    = rem - p*W_;
        int nin  = r / 9;
        int k9   = r - nin*9;
        int kr   = k9 / 3;
        int kc   = k9 - kr*3;
        const float4 t = *reinterpret_cast<const float4*>(
            x + ((((size_t)(b*NIN + nin)*H_ + (p+kr))*H_ + (q+kc))*CIN + half*4));
        *reinterpret_cast<float4*>(win + ((s*R_ + r)*CIN + half*4)) = t;
    }
    __syncthreads();

    // ---------------- P[s][o][r] = sum_i win[s][r][i] * rw[c][r][i][o] -------
    const float* rwc = rw + (size_t)c * R_ * CIN * COUT;
    for (int item = tid; item < R_*8; item += NT) {
        int r  = item >> 3;
        int s4 = (item >> 2) & 1;            // site half (sites 0-3 / 4-7)
        int o4 = item & 3;                   // output quad
        float Wv[CIN][4];
        const float* wp = rwc + (size_t)r*CIN*COUT + o4*4;
        #pragma unroll
        for (int i = 0; i < CIN; i++) {
            float4 t = *reinterpret_cast<const float4*>(wp + i*COUT);
            Wv[i][0]=t.x; Wv[i][1]=t.y; Wv[i][2]=t.z; Wv[i][3]=t.w;
        }
        #pragma unroll
        for (int ss = 0; ss < 4; ss++) {
            int s = s4*4 + ss;
            const float* wrow = win + (s*R_ + r)*CIN;
            float4 wa = *reinterpret_cast<const float4*>(wrow);
            float4 wb = *reinterpret_cast<const float4*>(wrow + 4);
            #pragma unroll
            for (int j = 0; j < 4; j++) {
                float acc =      wa.x * Wv[0][j];
                acc = fmaf(wa.y, Wv[1][j], acc);
                acc = fmaf(wa.z, Wv[2][j], acc);
                acc = fmaf(wa.w, Wv[3][j], acc);
                acc = fmaf(wb.x, Wv[4][j], acc);
                acc = fmaf(wb.y, Wv[5][j], acc);
                acc = fmaf(wb.z, Wv[6][j], acc);
                acc = fmaf(wb.w, Wv[7][j], acc);
                Ps[(s*COUT + o4*4 + j)*RS + r] = acc;
            }
        }
    }
    __syncthreads();   // win region now dead -> reused as a_s/v_s/red

    // ---------------- dynamic routing: 3 fused passes over P -----------------
    // pass 0: s = mean_r P            -> v0
    // pass 1: a1 = P·v0 (store), s = softmax(a1)-weighted sum -> v1
    // pass 2: a2 = a1 + P·v1,        s = softmax(a2)-weighted sum -> v2 = out
    const int sloc = tid >> 6;          // site 0..7 (2 warps per site)
    const int lane = tid & 63;          // r = lane + 64j
    const int wh   = (tid >> 5) & 1;    // which warp within the site group

    float v_reg[COUT];
    #pragma unroll
    for (int o = 0; o < COUT; o++) v_reg[o] = 0.f;

    for (int pass = 0; pass < 3; pass++) {
        if (pass > 0) {
            #pragma unroll
            for (int o = 0; o < COUT; o++) v_reg[o] = v_s[sloc*COUT + o];
        }
        float zloc = 0.f;
        float sv[COUT];
        #pragma unroll
        for (int o = 0; o < COUT; o++) sv[o] = 0.f;

        for (int r = lane; r < R_; r += 64) {
            float pv[COUT];
            #pragma unroll
            for (int o = 0; o < COUT; o++) pv[o] = Ps[(sloc*COUT + o)*RS + r];
            if (pass == 0) {
                #pragma unroll
                for (int o = 0; o < COUT; o++) sv[o] += pv[o];
            } else {
                float dot = 0.f;
                #pragma unroll
                for (int o = 0; o < COUT; o++) dot = fmaf(pv[o], v_reg[o], dot);
                float an = dot;
                if (pass == 2) an += a_s[sloc*R_ + r];
                else           a_s[sloc*R_ + r] = an;
                float e = __expf(an - 10.0f);   // fixed shift; cancels in ratio
                zloc += e;
                #pragma unroll
                for (int o = 0; o < COUT; o++) sv[o] = fmaf(e, pv[o], sv[o]);
            }
        }

        // reduce (z, sv[16]) across each warp
        #pragma unroll
        for (int off = 16; off > 0; off >>= 1) {
            zloc += __shfl_xor_sync(0xffffffffu, zloc, off);
            #pragma unroll
            for (int o = 0; o < COUT; o++)
                sv[o] += __shfl_xor_sync(0xffffffffu, sv[o], off);
        }
        if ((tid & 31) == 0) {
            float* rp = red + (sloc*2 + wh)*17;
            rp[0] = zloc;
            #pragma unroll
            for (int o = 0; o < COUT; o++) rp[1+o] = sv[o];
        }
        __syncthreads();

        // finalize: 128 threads, one per (site, o); squash via 16-lane shuffles
        if (tid < SB*COUT) {
            int s = tid >> 4;
            int o = tid & 15;
            float Z  = red[(s*2)*17]         + red[(s*2+1)*17];
            float so = red[(s*2)*17 + 1 + o] + red[(s*2+1)*17 + 1 + o];
            so *= (pass == 0) ? (1.0f/(float)R_) : (1.0f/Z);
            float sn = so*so;
            #pragma unroll
            for (int off = 8; off > 0; off >>= 1)
                sn += __shfl_xor_sync(0xffffffffu, sn, off);
            float vv = so * (sqrtf(sn) / (1.0f + sn));
            if (pass < 2) {
                v_s[s*COUT + o] = vv;
            } else {
                int site = sb*SB + s;
                int b    = site / (W_*W_);
                int rem  = site - b*(W_*W_);
                int p    = rem / W_;
                int q    = rem - p*W_;
                // out layout: (B, C, w, w, Cout)
                out[((((size_t)b*C_ + c)*W_ + p)*W_ + q)*COUT + o] = vv;
            }
        }
        __syncthreads();
    }
}

extern "C" void kernel_launch(void* const* d_in, const int* in_sizes, int n_in,
                              void* d_out, int out_size)
{
    const float* x  = (const float*)d_in[0];
    const float* rw = (const float*)d_in[1];
    // defensive: identify by element count (x=401408, rw=1179648)
    if (n_in >= 2 && in_sizes[0] == C_*R_*CIN*COUT) {
        const float* t = x; x = rw; rw = t;
    }
    float* out = (float*)d_out;

    const size_t smem = (size_t)SM_FLOATS * sizeof(float);   // 222,208 B
    cudaFuncSetAttribute(caps_kernel,
                         cudaFuncAttributeMaxDynamicSharedMemorySize, (int)smem);

    dim3 grid(B_*W_*W_/SB, C_);   // (144, 32) = 4608 CTAs
    caps_kernel<<<grid, NT, smem>>>(x, rw, out);
}